// round 11
// baseline (speedup 1.0000x reference)
#include <cuda_runtime.h>
#include <cuda_bf16.h>
#include <cstdint>
#include <math.h>

// Problem constants
#define C_   8
#define NQ_  16
#define NK_  32
#define B_   128
#define D_   128
#define E_   512
#define H_   8
#define A_   64
#define OUT_ 64

// Scratch (allocation-free rule: device globals)
__device__ float g_query[C_ * NQ_ * B_ * E_];    // 33.5 MB
__device__ float g_key  [C_ * NK_ * B_ * E_];    // 67 MB
__device__ float g_value[C_ * NK_ * B_ * E_];    // 67 MB
__device__ float g_attno[C_ * NQ_ * B_ * E_];    // 33.5 MB

// ===========================================================================
// Helpers
// ===========================================================================
__device__ __forceinline__ uint32_t smem_to_u32(const void* p) {
    uint32_t a;
    asm("{ .reg .u64 t; cvta.to.shared.u64 t, %1; cvt.u32.u64 %0, t; }"
        : "=r"(a) : "l"(p));
    return a;
}

// ldmatrix: 8x8 b16 matrices (baseline PTX, sm_75+)
#define LDSM_X4(r, addr) \
    asm volatile("ldmatrix.sync.aligned.m8n8.x4.shared.b16 {%0,%1,%2,%3}, [%4];" \
        : "=r"((r)[0]), "=r"((r)[1]), "=r"((r)[2]), "=r"((r)[3]) : "r"(addr))
#define LDSM_X4_T(r, addr) \
    asm volatile("ldmatrix.sync.aligned.m8n8.x4.trans.shared.b16 {%0,%1,%2,%3}, [%4];" \
        : "=r"((r)[0]), "=r"((r)[1]), "=r"((r)[2]), "=r"((r)[3]) : "r"(addr))

// mma.sync m16n8k16 bf16 -> f32 (baseline PTX, sm_80+)
#define MMA_BF16(d, a, b0, b1) \
    asm volatile("mma.sync.aligned.m16n8k16.row.col.f32.bf16.bf16.f32 " \
        "{%0,%1,%2,%3}, {%4,%5,%6,%7}, {%8,%9}, {%0,%1,%2,%3};" \
        : "+f"((d)[0]), "+f"((d)[1]), "+f"((d)[2]), "+f"((d)[3]) \
        : "r"((a)[0]), "r"((a)[1]), "r"((a)[2]), "r"((a)[3]), \
          "r"(b0), "r"(b1))

// cp.async (baseline PTX, sm_80+)
#define CP_ASYNC16(saddr, gptr) \
    asm volatile("cp.async.cg.shared.global [%0], [%1], 16;" \
        :: "r"(saddr), "l"(gptr) : "memory")
#define CP_COMMIT() asm volatile("cp.async.commit_group;" ::: "memory")
#define CP_WAIT0()  asm volatile("cp.async.wait_group 0;" ::: "memory")

// Tile smem layout: [rows][128 bf16] = 256 B/row, 16B chunks swizzled by
// (chunk ^ (row & 7)) so ldmatrix's 8-row column access is conflict-free.
__device__ __forceinline__ uint32_t toff(int row, int kk) {
    return ((uint32_t)row << 8)
         + ((uint32_t)(((kk >> 3) ^ (row & 7))) << 4)
         + ((uint32_t)(kk & 7) << 1);
}

// Split fp32 pair -> packed bf16x2 hi and lo words
__device__ __forceinline__ void split2(float a, float b, uint32_t& hi, uint32_t& lo) {
    __nv_bfloat16 h0 = __float2bfloat16(a);
    __nv_bfloat16 h1 = __float2bfloat16(b);
    float r0 = a - __bfloat162float(h0);
    float r1 = b - __bfloat162float(h1);
    __nv_bfloat16 l0 = __float2bfloat16(r0);
    __nv_bfloat16 l1 = __float2bfloat16(r1);
    hi = (uint32_t)__bfloat16_as_ushort(h0) | ((uint32_t)__bfloat16_as_ushort(h1) << 16);
    lo = (uint32_t)__bfloat16_as_ushort(l0) | ((uint32_t)__bfloat16_as_ushort(l1) << 16);
}

// ---- qkv dynamic smem layout (bytes) ----
#define SM_PE     0          // 512 B
#define SM_AHI    1024       // 32 KB  A: [m 128][k 128] bf16
#define SM_ALO    33792      // 32 KB
#define SM_BHI    66560      // 32 KB  B: [k 128][n 128] bf16 (natural layout)
#define SM_BLO    99328      // 32 KB
#define SM_WRAW   132096     // 64 KB  raw fp32 W slab (cp.async target)
#define SM_TOTAL  197632

// ---------------------------------------------------------------------------
// Kernel 1: split-bf16 HMMA fused QKV projection with positional encoding.
// grid = 640: [0,128) Q, [128,384) K, [384,640) V. 512 threads, 1 CTA/SM.
// cp.async pipelining: raw W slab (s+1) streams into SM_WRAW during the MMA
// burst of slab s; the split phase reads smem instead of global (fix for
// staging-latency exposure: tensor=38%, issue=17.8% in R9).
// D = Ahi*Bhi + Ahi*Blo + Alo*Bhi, fp32 register accumulate.
// Warp grid 2(M) x 8(N); warp tile 64x16 = 4x2 m16n8 tiles.
// ---------------------------------------------------------------------------
__global__ __launch_bounds__(512, 1) void qkv_mma_kernel(
    const float* __restrict__ q, const float* __restrict__ k,
    const float* __restrict__ Wq, const float* __restrict__ Wk,
    const float* __restrict__ Wv)
{
    extern __shared__ char smem[];
    uint32_t sbase = smem_to_u32(smem);
    int t = threadIdx.x, wid = t >> 5, lane = t & 31;

    int bid = blockIdx.x;
    const float* X; const float* W; float* Out; int n;
    if (bid < 128) {
        int i = bid; int c = i >> 4; n = i & 15;
        X = q  + (size_t)(c * NQ_ + n) * B_ * D_;
        W = Wq + (size_t)(c * NQ_ + n) * D_ * E_;
        Out = g_query + (size_t)(c * NQ_ + n) * B_ * E_;
    } else if (bid < 384) {
        int i = bid - 128; int c = i >> 5; n = i & 31;
        X = k  + (size_t)(c * NK_ + n) * B_ * D_;
        W = Wk + (size_t)(c * NK_ + n) * D_ * E_;
        Out = g_key + (size_t)(c * NK_ + n) * B_ * E_;
    } else {
        int i = bid - 384; int c = i >> 5; n = i & 31;
        X = k  + (size_t)(c * NK_ + n) * B_ * D_;
        W = Wv + (size_t)(c * NK_ + n) * D_ * E_;
        Out = g_value + (size_t)(c * NK_ + n) * B_ * E_;
    }

    // Prefetch raw W slab 0 ASAP (overlaps PE + A staging below).
    {
#pragma unroll
        for (int j = 0; j < 8; j++) {
            int it = t + 512 * j;          // 4096 16B chunks
            int ch = it & 31; int krow = it >> 5;
            uint32_t sa = sbase + SM_WRAW + ((uint32_t)krow << 9) + ((uint32_t)ch << 4);
            CP_ASYNC16(sa, W + (size_t)krow * E_ + ch * 4);
        }
        CP_COMMIT();
    }

    float* pe = (float*)(smem + SM_PE);
    if (t < 128) {
        const float kc = -9.210340371976184f / 128.0f;  // -ln(10000)/D
        float w = expf((float)(t & ~1) * kc);
        pe[t] = (t & 1) ? cosf((float)n * w) : sinf((float)n * w);
    }
    __syncthreads();

    // ---- Stage A = X + PE (128 x 128), split hi/lo, [m][k] layout ----
#pragma unroll
    for (int j = 0; j < 8; j++) {
        int it  = t + 512 * j;            // 4096 float4 items
        int row = it >> 5;                // m: 0..127
        int kk  = (it & 31) * 4;          // k: 0..124
        float4 v = *(const float4*)(X + (size_t)row * D_ + kk);
        v.x += pe[kk]; v.y += pe[kk + 1]; v.z += pe[kk + 2]; v.w += pe[kk + 3];
        uint32_t h0, l0, h1, l1;
        split2(v.x, v.y, h0, l0);
        split2(v.z, v.w, h1, l1);
        uint32_t off = toff(row, kk);
        *(uint2*)(smem + SM_AHI + off) = make_uint2(h0, h1);
        *(uint2*)(smem + SM_ALO + off) = make_uint2(l0, l1);
    }

    int m0 = (wid >> 3) * 64;     // warp M origin (0 or 64)
    int n0 = (wid & 7) * 16;      // warp N origin within slab

    int a_row_lo  = lane & 15;
    int a_chsel   = lane >> 4;
    int b_mat     = lane >> 3;
    int b_krow_lo = (b_mat & 1) * 8 + (lane & 7);
    int b_nch     = (n0 >> 3) + (b_mat >> 1);

    for (int slab = 0; slab < 4; slab++) {
        // ---- Wait for this slab's raw W, then split from smem ----
        CP_WAIT0();
        __syncthreads();
#pragma unroll
        for (int j = 0; j < 4; j++) {
            int it   = t + 512 * j;       // 2048 items
            int nch  = it & 15;           // n-chunk: 0..15
            int krow = it >> 4;           // k: 0..127
            const char* raw = smem + SM_WRAW + ((uint32_t)krow << 9) + nch * 32;
            float4 w0 = *(const float4*)(raw);
            float4 w1 = *(const float4*)(raw + 16);
            uint32_t h0, l0, h1, l1, h2, l2, h3, l3;
            split2(w0.x, w0.y, h0, l0);
            split2(w0.z, w0.w, h1, l1);
            split2(w1.x, w1.y, h2, l2);
            split2(w1.z, w1.w, h3, l3);
            uint32_t off = ((uint32_t)krow << 8)
                         + ((uint32_t)((nch ^ (krow & 7))) << 4);
            *(uint4*)(smem + SM_BHI + off) = make_uint4(h0, h1, h2, h3);
            *(uint4*)(smem + SM_BLO + off) = make_uint4(l0, l1, l2, l3);
        }
        __syncthreads();   // B tiles ready; WRAW free for next prefetch

        // ---- Prefetch next slab's raw W (overlaps MMA burst) ----
        if (slab < 3) {
            const float* Wn = W + (slab + 1) * 128;
#pragma unroll
            for (int j = 0; j < 8; j++) {
                int it = t + 512 * j;
                int ch = it & 31; int krow = it >> 5;
                uint32_t sa = sbase + SM_WRAW + ((uint32_t)krow << 9) + ((uint32_t)ch << 4);
                CP_ASYNC16(sa, Wn + (size_t)krow * E_ + ch * 4);
            }
            CP_COMMIT();
        }

        // ---- MMA burst: 8 k-steps x 4x2 tiles x 3 split terms ----
        float acc[4][2][4];
#pragma unroll
        for (int mt = 0; mt < 4; mt++)
#pragma unroll
            for (int nt = 0; nt < 2; nt++)
#pragma unroll
                for (int r = 0; r < 4; r++) acc[mt][nt][r] = 0.f;

#pragma unroll
        for (int ks = 0; ks < 8; ks++) {
            uint32_t bh[4], bl[4];
            {
                int krow = ks * 16 + b_krow_lo;
                uint32_t off = ((uint32_t)krow << 8)
                             + ((uint32_t)((b_nch ^ (krow & 7))) << 4);
                LDSM_X4_T(bh, sbase + SM_BHI + off);
                LDSM_X4_T(bl, sbase + SM_BLO + off);
            }
#pragma unroll
            for (int mt = 0; mt < 4; mt++) {
                int row = m0 + mt * 16 + a_row_lo;
                uint32_t ch = (uint32_t)(ks * 2 + a_chsel);
                uint32_t off = ((uint32_t)row << 8) + (((ch ^ (row & 7))) << 4);
                uint32_t ah[4], al[4];
                LDSM_X4(ah, sbase + SM_AHI + off);
                LDSM_X4(al, sbase + SM_ALO + off);
                MMA_BF16(acc[mt][0], ah, bh[0], bh[1]);
                MMA_BF16(acc[mt][0], ah, bl[0], bl[1]);
                MMA_BF16(acc[mt][0], al, bh[0], bh[1]);
                MMA_BF16(acc[mt][1], ah, bh[2], bh[3]);
                MMA_BF16(acc[mt][1], ah, bl[2], bl[3]);
                MMA_BF16(acc[mt][1], al, bh[2], bh[3]);
            }
        }

        // ---- Epilogue: direct fp32 stores ----
#pragma unroll
        for (int mt = 0; mt < 4; mt++) {
            int row = m0 + mt * 16 + (lane >> 2);
#pragma unroll
            for (int nt = 0; nt < 2; nt++) {
                int col = slab * 128 + n0 + nt * 8 + (lane & 3) * 2;
                float2 v0 = make_float2(acc[mt][nt][0], acc[mt][nt][1]);
                float2 v1 = make_float2(acc[mt][nt][2], acc[mt][nt][3]);
                *(float2*)(Out + (size_t)row * E_ + col) = v0;
                *(float2*)(Out + (size_t)(row + 8) * E_ + col) = v1;
            }
        }
        // next loop iteration's __syncthreads (after CP_WAIT0) protects B tiles
    }
}

// ---------------------------------------------------------------------------
// Kernel 2: attention per (c, b, h). grid = 8192, 128 threads. (unchanged)
// ---------------------------------------------------------------------------
__global__ __launch_bounds__(128) void attn_kernel()
{
    int bid = blockIdx.x;
    int h = bid & 7;
    int b = (bid >> 3) & 127;
    int c = bid >> 10;
    int t = threadIdx.x;

    __shared__ float Qs[16 * 64];
    __shared__ float Ks[32 * 68];
    __shared__ float Vs[32 * 64];
    __shared__ float lg[16 * 33];
    __shared__ float rmax[16], rsum[16];

#pragma unroll
    for (int j = 0; j < 2; j++) {
        int i4 = t + 128 * j;
        int nq = i4 >> 4, a4 = i4 & 15;
        *(float4*)&Qs[nq * 64 + a4 * 4] =
            *(const float4*)(g_query + (size_t)((c * NQ_ + nq) * B_ + b) * E_ + h * A_ + a4 * 4);
    }
#pragma unroll
    for (int j = 0; j < 4; j++) {
        int i4 = t + 128 * j;
        int nk = i4 >> 4, a4 = i4 & 15;
        size_t goff = (size_t)((c * NK_ + nk) * B_ + b) * E_ + h * A_ + a4 * 4;
        *(float4*)&Ks[nk * 68 + a4 * 4] = *(const float4*)(g_key + goff);
        *(float4*)&Vs[nk * 64 + a4 * 4] = *(const float4*)(g_value + goff);
    }
    __syncthreads();

    int nk  = t & 31;
    int nq0 = t >> 5;
    {
        float s0 = 0.f, s1 = 0.f, s2 = 0.f, s3 = 0.f;
#pragma unroll
        for (int a4 = 0; a4 < 16; a4++) {
            float4 kv = *(const float4*)&Ks[nk * 68 + a4 * 4];
            float4 q0 = *(const float4*)&Qs[(nq0 + 0)  * 64 + a4 * 4];
            float4 q1 = *(const float4*)&Qs[(nq0 + 4)  * 64 + a4 * 4];
            float4 q2 = *(const float4*)&Qs[(nq0 + 8)  * 64 + a4 * 4];
            float4 q3 = *(const float4*)&Qs[(nq0 + 12) * 64 + a4 * 4];
            s0 += q0.x * kv.x + q0.y * kv.y + q0.z * kv.z + q0.w * kv.w;
            s1 += q1.x * kv.x + q1.y * kv.y + q1.z * kv.z + q1.w * kv.w;
            s2 += q2.x * kv.x + q2.y * kv.y + q2.z * kv.z + q2.w * kv.w;
            s3 += q3.x * kv.x + q3.y * kv.y + q3.z * kv.z + q3.w * kv.w;
        }
        const float inv_temp = 0.125f;
        lg[(nq0 + 0)  * 33 + nk] = s0 * inv_temp;
        lg[(nq0 + 4)  * 33 + nk] = s1 * inv_temp;
        lg[(nq0 + 8)  * 33 + nk] = s2 * inv_temp;
        lg[(nq0 + 12) * 33 + nk] = s3 * inv_temp;
    }
    __syncthreads();

    if (t < 16) {
        float m = -3.4028234e38f;
        for (int x = 0; x < 32; x++) m = fmaxf(m, lg[t * 33 + x]);
        rmax[t] = m;
    }
    __syncthreads();

#pragma unroll
    for (int j = 0; j < 4; j++) {
        int nq = nq0 + 4 * j;
        int id = nq * 33 + nk;
        lg[id] = expf(lg[id] - rmax[nq]);
    }
    __syncthreads();

    if (t < 16) {
        float s = 0.f;
        for (int x = 0; x < 32; x++) s += lg[t * 33 + x];
        rsum[t] = s;
    }
    __syncthreads();

    int a   = t & 63;
    int nqb = t >> 6;
    float racc[8];
#pragma unroll
    for (int j = 0; j < 8; j++) racc[j] = 0.f;
#pragma unroll
    for (int x = 0; x < 32; x++) {
        float v = Vs[x * 64 + a];
#pragma unroll
        for (int j = 0; j < 8; j++)
            racc[j] += lg[(nqb + 2 * j) * 33 + x] * v;
    }
#pragma unroll
    for (int j = 0; j < 8; j++) {
        int nq = nqb + 2 * j;
        g_attno[(size_t)((c * NQ_ + nq) * B_ + b) * E_ + h * A_ + a] = racc[j] / rsum[nq];
    }
}

// ---------------------------------------------------------------------------
// Kernel 3: split-bf16 HMMA output projection.
// grid = 256: (c, nq, mtile). Block: [64 b x 512 e] @ [512 e x 64 o],
// K-slab accumulation (4 slabs of 128). 256 threads, 8 warps 2(M)x4(N),
// warp tile 32x16 = 2x2 m16n8. smem 64 KB -> 2 CTAs/SM.
// A: [m 64][k 128] bf16 hi/lo; B: [k 128][n 64] bf16 hi/lo (natural layout).
// ---------------------------------------------------------------------------
#define PJ_AHI   0          // 16 KB
#define PJ_ALO   16384      // 16 KB
#define PJ_BHI   32768      // 16 KB
#define PJ_BLO   49152      // 16 KB
#define PJ_TOTAL 65536

__global__ __launch_bounds__(256, 2) void proj_mma_kernel(
    const float* __restrict__ Wp, float* __restrict__ out)
{
    extern __shared__ char smem[];
    uint32_t sbase = smem_to_u32(smem);
    int t = threadIdx.x, wid = t >> 5, lane = t & 31;

    int bid   = blockIdx.x;
    int mtile = bid & 1;
    int gm    = bid >> 1;
    int nq    = gm & 15;
    int c     = gm >> 4;

    const float* Ap = g_attno + (size_t)((c * NQ_ + nq) * B_ + mtile * 64) * E_;  // ld=512
    const float* Bp = Wp + (size_t)(c * NQ_ + nq) * E_ * OUT_;                    // ld=64
    float*       Op = out + (size_t)((c * NQ_ + nq) * B_ + mtile * 64) * OUT_;    // ld=64

    int m0 = (wid >> 2) * 32;     // 0 or 32
    int n0 = (wid & 3) * 16;      // 0,16,32,48

    int a_row_lo  = lane & 15;
    int a_chsel   = lane >> 4;
    int b_mat     = lane >> 3;
    int b_krow_lo = (b_mat & 1) * 8 + (lane & 7);
    int b_nch     = (n0 >> 3) + (b_mat >> 1);    // 0..7

    float acc[2][2][4];
#pragma unroll
    for (int mt = 0; mt < 2; mt++)
#pragma unroll
        for (int nt = 0; nt < 2; nt++)
#pragma unroll
            for (int r = 0; r < 4; r++) acc[mt][nt][r] = 0.f;

    for (int kslab = 0; kslab < 4; kslab++) {
        if (kslab) __syncthreads();   // protect previous slab's tiles

        // ---- Stage A slab: 64 rows x 128 k, split hi/lo ----
#pragma unroll
        for (int j = 0; j < 8; j++) {
            int it  = t + 256 * j;        // 2048 float4 items
            int row = it >> 5;            // 0..63
            int kk  = (it & 31) * 4;      // 0..124
            float4 v = *(const float4*)(Ap + (size_t)row * E_ + kslab * 128 + kk);
            uint32_t h0, l0, h1, l1;
            split2(v.x, v.y, h0, l0);
            split2(v.z, v.w, h1, l1);
            uint32_t off = toff(row, kk);
            *(uint2*)(smem + PJ_AHI + off) = make_uint2(h0, h1);
            *(uint2*)(smem + PJ_ALO + off) = make_uint2(l0, l1);
        }
        // ---- Stage B slab: 128 k-rows x 64 n, natural [k][n], hi/lo ----
#pragma unroll
        for (int j = 0; j < 4; j++) {
            int it   = t + 256 * j;       // 1024 items
            int nch  = it & 7;            // 0..7 (8-wide n chunk)
            int krow = it >> 3;           // 0..127
            const float* src = Bp + (size_t)(kslab * 128 + krow) * OUT_ + nch * 8;
            float4 w0 = *(const float4*)(src);
            float4 w1 = *(const float4*)(src + 4);
            uint32_t h0, l0, h1, l1, h2, l2, h3, l3;
            split2(w0.x, w0.y, h0, l0);
            split2(w0.z, w0.w, h1, l1);
            split2(w1.x, w1.y, h2, l2);
            split2(w1.z, w1.w, h3, l3);
            uint32_t off = ((uint32_t)krow << 7)
                         + ((uint32_t)((nch ^ (krow & 7))) << 4);
            *(uint4*)(smem + PJ_BHI + off) = make_uint4(h0, h1, h2, h3);
            *(uint4*)(smem + PJ_BLO + off) = make_uint4(l0, l1, l2, l3);
        }
        __syncthreads();

        // ---- MMA: 8 k-steps x 2x2 tiles x 3 split terms ----
#pragma unroll
        for (int ks = 0; ks < 8; ks++) {
            uint32_t bh[4], bl[4];
            {
                int krow = ks * 16 + b_krow_lo;
                uint32_t off = ((uint32_t)krow << 7)
                             + ((uint32_t)((b_nch ^ (krow & 7))) << 4);
                LDSM_X4_T(bh, sbase + PJ_BHI + off);
                LDSM_X4_T(bl, sbase + PJ_BLO + off);
            }
#pragma unroll
            for (int mt = 0; mt < 2; mt++) {
                int row = m0 + mt * 16 + a_row_lo;
                uint32_t ch = (uint32_t)(ks * 2 + a_chsel);
                uint32_t off = ((uint32_t)row << 8) + (((ch ^ (row & 7))) << 4);
                uint32_t ah[4], al[4];
                LDSM_X4(ah, sbase + PJ_AHI + off);
                LDSM_X4(al, sbase + PJ_ALO + off);
                MMA_BF16(acc[mt][0], ah, bh[0], bh[1]);
                MMA_BF16(acc[mt][0], ah, bl[0], bl[1]);
                MMA_BF16(acc[mt][0], al, bh[0], bh[1]);
                MMA_BF16(acc[mt][1], ah, bh[2], bh[3]);
                MMA_BF16(acc[mt][1], ah, bl[2], bl[3]);
                MMA_BF16(acc[mt][1], al, bh[2], bh[3]);
            }
        }
    }

    // ---- Epilogue ----
#pragma unroll
    for (int mt = 0; mt < 2; mt++) {
        int row = m0 + mt * 16 + (lane >> 2);
#pragma unroll
        for (int nt = 0; nt < 2; nt++) {
            int col = n0 + nt * 8 + (lane & 3) * 2;
            float2 v0 = make_float2(acc[mt][nt][0], acc[mt][nt][1]);
            float2 v1 = make_float2(acc[mt][nt][2], acc[mt][nt][3]);
            *(float2*)(Op + (size_t)row * OUT_ + col) = v0;
            *(float2*)(Op + (size_t)(row + 8) * OUT_ + col) = v1;
        }
    }
}

// ---------------------------------------------------------------------------
extern "C" void kernel_launch(void* const* d_in, const int* in_sizes, int n_in,
                              void* d_out, int out_size)
{
    (void)in_sizes; (void)n_in; (void)out_size;
    const float* q  = (const float*)d_in[0];
    const float* k  = (const float*)d_in[1];
    const float* Wq = (const float*)d_in[2];
    const float* Wk = (const float*)d_in[3];
    const float* Wv = (const float*)d_in[4];
    const float* Wp = (const float*)d_in[5];
    float* out = (float*)d_out;

    cudaFuncSetAttribute(qkv_mma_kernel,
                         cudaFuncAttributeMaxDynamicSharedMemorySize, SM_TOTAL);
    cudaFuncSetAttribute(proj_mma_kernel,
                         cudaFuncAttributeMaxDynamicSharedMemorySize, PJ_TOTAL);

    qkv_mma_kernel<<<640, 512, SM_TOTAL>>>(q, k, Wq, Wk, Wv);
    attn_kernel<<<8192, 128>>>();
    proj_mma_kernel<<<256, 256, PJ_TOTAL>>>(Wp, out);
}

// round 12
// speedup vs baseline: 1.4981x; 1.4981x over previous
#include <cuda_runtime.h>
#include <cuda_bf16.h>
#include <cstdint>
#include <math.h>

// Problem constants
#define C_   8
#define NQ_  16
#define NK_  32
#define B_   128
#define D_   128
#define E_   512
#define H_   8
#define A_   64
#define OUT_ 64

// Scratch (allocation-free rule: device globals)
__device__ float g_query[C_ * NQ_ * B_ * E_];    // 33.5 MB
__device__ float g_key  [C_ * NK_ * B_ * E_];    // 67 MB
__device__ float g_value[C_ * NK_ * B_ * E_];    // 67 MB
__device__ float g_attno[C_ * NQ_ * B_ * E_];    // 33.5 MB

// ===========================================================================
// Helpers
// ===========================================================================
__device__ __forceinline__ uint32_t smem_to_u32(const void* p) {
    uint32_t a;
    asm("{ .reg .u64 t; cvta.to.shared.u64 t, %1; cvt.u32.u64 %0, t; }"
        : "=r"(a) : "l"(p));
    return a;
}

// ldmatrix: 8x8 b16 matrices (baseline PTX, sm_75+)
#define LDSM_X4(r, addr) \
    asm volatile("ldmatrix.sync.aligned.m8n8.x4.shared.b16 {%0,%1,%2,%3}, [%4];" \
        : "=r"((r)[0]), "=r"((r)[1]), "=r"((r)[2]), "=r"((r)[3]) : "r"(addr))
#define LDSM_X4_T(r, addr) \
    asm volatile("ldmatrix.sync.aligned.m8n8.x4.trans.shared.b16 {%0,%1,%2,%3}, [%4];" \
        : "=r"((r)[0]), "=r"((r)[1]), "=r"((r)[2]), "=r"((r)[3]) : "r"(addr))

// mma.sync m16n8k16 bf16 -> f32 (baseline PTX, sm_80+)
#define MMA_BF16(d, a, b0, b1) \
    asm volatile("mma.sync.aligned.m16n8k16.row.col.f32.bf16.bf16.f32 " \
        "{%0,%1,%2,%3}, {%4,%5,%6,%7}, {%8,%9}, {%0,%1,%2,%3};" \
        : "+f"((d)[0]), "+f"((d)[1]), "+f"((d)[2]), "+f"((d)[3]) \
        : "r"((a)[0]), "r"((a)[1]), "r"((a)[2]), "r"((a)[3]), \
          "r"(b0), "r"(b1))

// Tile smem layout: [rows][128 bf16] = 256 B/row, 16B chunks swizzled by
// (chunk ^ (row & 7)) so ldmatrix's 8-row column access is conflict-free.
__device__ __forceinline__ uint32_t toff(int row, int kk) {
    return ((uint32_t)row << 8)
         + ((uint32_t)(((kk >> 3) ^ (row & 7))) << 4)
         + ((uint32_t)(kk & 7) << 1);
}

// Split fp32 pair -> packed bf16x2 hi and lo words
__device__ __forceinline__ void split2(float a, float b, uint32_t& hi, uint32_t& lo) {
    __nv_bfloat16 h0 = __float2bfloat16(a);
    __nv_bfloat16 h1 = __float2bfloat16(b);
    float r0 = a - __bfloat162float(h0);
    float r1 = b - __bfloat162float(h1);
    __nv_bfloat16 l0 = __float2bfloat16(r0);
    __nv_bfloat16 l1 = __float2bfloat16(r1);
    hi = (uint32_t)__bfloat16_as_ushort(h0) | ((uint32_t)__bfloat16_as_ushort(h1) << 16);
    lo = (uint32_t)__bfloat16_as_ushort(l0) | ((uint32_t)__bfloat16_as_ushort(l1) << 16);
}

// ---- qkv dynamic smem layout (bytes) ----
#define SM_PE     0          // 512 B
#define SM_AHI    1024       // 32 KB  A: [m 128][k 128] bf16
#define SM_ALO    33792      // 32 KB
#define SM_BHI    66560      // 32 KB  B: [k 128][n 128] bf16 (natural layout)
#define SM_BLO    99328      // 32 KB
#define SM_TOTAL  132096

// ---------------------------------------------------------------------------
// Kernel 1: split-bf16 HMMA fused QKV projection (exact R9 revert — the
// cp.async variant regressed via LSU contention).
// grid = 640: [0,128) Q, [128,384) K, [384,640) V. 512 threads, 1 CTA/SM.
// D = Ahi*Bhi + Ahi*Blo + Alo*Bhi, fp32 register accumulate.
// Warp grid 2(M) x 8(N); warp tile 64x16 = 4x2 m16n8 tiles.
// ---------------------------------------------------------------------------
__global__ __launch_bounds__(512, 1) void qkv_mma_kernel(
    const float* __restrict__ q, const float* __restrict__ k,
    const float* __restrict__ Wq, const float* __restrict__ Wk,
    const float* __restrict__ Wv)
{
    extern __shared__ char smem[];
    uint32_t sbase = smem_to_u32(smem);
    int t = threadIdx.x, wid = t >> 5, lane = t & 31;

    int bid = blockIdx.x;
    const float* X; const float* W; float* Out; int n;
    if (bid < 128) {
        int i = bid; int c = i >> 4; n = i & 15;
        X = q  + (size_t)(c * NQ_ + n) * B_ * D_;
        W = Wq + (size_t)(c * NQ_ + n) * D_ * E_;
        Out = g_query + (size_t)(c * NQ_ + n) * B_ * E_;
    } else if (bid < 384) {
        int i = bid - 128; int c = i >> 5; n = i & 31;
        X = k  + (size_t)(c * NK_ + n) * B_ * D_;
        W = Wk + (size_t)(c * NK_ + n) * D_ * E_;
        Out = g_key + (size_t)(c * NK_ + n) * B_ * E_;
    } else {
        int i = bid - 384; int c = i >> 5; n = i & 31;
        X = k  + (size_t)(c * NK_ + n) * B_ * D_;
        W = Wv + (size_t)(c * NK_ + n) * D_ * E_;
        Out = g_value + (size_t)(c * NK_ + n) * B_ * E_;
    }

    float* pe = (float*)(smem + SM_PE);
    if (t < 128) {
        const float kc = -9.210340371976184f / 128.0f;  // -ln(10000)/D
        float w = expf((float)(t & ~1) * kc);
        pe[t] = (t & 1) ? cosf((float)n * w) : sinf((float)n * w);
    }
    __syncthreads();

    // ---- Stage A = X + PE (128 x 128), split hi/lo, [m][k] layout ----
#pragma unroll
    for (int j = 0; j < 8; j++) {
        int it  = t + 512 * j;            // 4096 float4 items
        int row = it >> 5;                // m: 0..127
        int kk  = (it & 31) * 4;          // k: 0..124
        float4 v = *(const float4*)(X + (size_t)row * D_ + kk);
        v.x += pe[kk]; v.y += pe[kk + 1]; v.z += pe[kk + 2]; v.w += pe[kk + 3];
        uint32_t h0, l0, h1, l1;
        split2(v.x, v.y, h0, l0);
        split2(v.z, v.w, h1, l1);
        uint32_t off = toff(row, kk);
        *(uint2*)(smem + SM_AHI + off) = make_uint2(h0, h1);
        *(uint2*)(smem + SM_ALO + off) = make_uint2(l0, l1);
    }

    int m0 = (wid >> 3) * 64;     // warp M origin (0 or 64)
    int n0 = (wid & 7) * 16;      // warp N origin within slab

    int a_row_lo  = lane & 15;
    int a_chsel   = lane >> 4;
    int b_mat     = lane >> 3;
    int b_krow_lo = (b_mat & 1) * 8 + (lane & 7);
    int b_nch     = (n0 >> 3) + (b_mat >> 1);

    for (int slab = 0; slab < 4; slab++) {
        const float* Wp = W + slab * 128;

        // ---- Stage B = W-slab (128k x 128n), natural [k][n], hi/lo ----
#pragma unroll
        for (int j = 0; j < 4; j++) {
            int it   = t + 512 * j;       // 2048 items
            int nch  = it & 15;           // n-chunk: 0..15
            int krow = it >> 4;           // k: 0..127
            const float* src = Wp + (size_t)krow * E_ + nch * 8;
            float4 w0 = *(const float4*)(src);
            float4 w1 = *(const float4*)(src + 4);
            uint32_t h0, l0, h1, l1, h2, l2, h3, l3;
            split2(w0.x, w0.y, h0, l0);
            split2(w0.z, w0.w, h1, l1);
            split2(w1.x, w1.y, h2, l2);
            split2(w1.z, w1.w, h3, l3);
            uint32_t off = ((uint32_t)krow << 8)
                         + ((uint32_t)((nch ^ (krow & 7))) << 4);
            *(uint4*)(smem + SM_BHI + off) = make_uint4(h0, h1, h2, h3);
            *(uint4*)(smem + SM_BLO + off) = make_uint4(l0, l1, l2, l3);
        }
        __syncthreads();

        // ---- MMA burst: 8 k-steps x 4x2 tiles x 3 split terms ----
        float acc[4][2][4];
#pragma unroll
        for (int mt = 0; mt < 4; mt++)
#pragma unroll
            for (int nt = 0; nt < 2; nt++)
#pragma unroll
                for (int r = 0; r < 4; r++) acc[mt][nt][r] = 0.f;

#pragma unroll
        for (int ks = 0; ks < 8; ks++) {
            uint32_t bh[4], bl[4];
            {
                int krow = ks * 16 + b_krow_lo;
                uint32_t off = ((uint32_t)krow << 8)
                             + ((uint32_t)((b_nch ^ (krow & 7))) << 4);
                LDSM_X4_T(bh, sbase + SM_BHI + off);
                LDSM_X4_T(bl, sbase + SM_BLO + off);
            }
#pragma unroll
            for (int mt = 0; mt < 4; mt++) {
                int row = m0 + mt * 16 + a_row_lo;
                uint32_t ch = (uint32_t)(ks * 2 + a_chsel);
                uint32_t off = ((uint32_t)row << 8) + (((ch ^ (row & 7))) << 4);
                uint32_t ah[4], al[4];
                LDSM_X4(ah, sbase + SM_AHI + off);
                LDSM_X4(al, sbase + SM_ALO + off);
                MMA_BF16(acc[mt][0], ah, bh[0], bh[1]);
                MMA_BF16(acc[mt][0], ah, bl[0], bl[1]);
                MMA_BF16(acc[mt][0], al, bh[0], bh[1]);
                MMA_BF16(acc[mt][1], ah, bh[2], bh[3]);
                MMA_BF16(acc[mt][1], ah, bl[2], bl[3]);
                MMA_BF16(acc[mt][1], al, bh[2], bh[3]);
            }
        }

        // ---- Epilogue: direct fp32 stores ----
#pragma unroll
        for (int mt = 0; mt < 4; mt++) {
            int row = m0 + mt * 16 + (lane >> 2);
#pragma unroll
            for (int nt = 0; nt < 2; nt++) {
                int col = slab * 128 + n0 + nt * 8 + (lane & 3) * 2;
                float2 v0 = make_float2(acc[mt][nt][0], acc[mt][nt][1]);
                float2 v1 = make_float2(acc[mt][nt][2], acc[mt][nt][3]);
                *(float2*)(Out + (size_t)row * E_ + col) = v0;
                *(float2*)(Out + (size_t)(row + 8) * E_ + col) = v1;
            }
        }
        if (slab < 3) __syncthreads();   // B tiles consumed before restaging
    }
}

// ---------------------------------------------------------------------------
// Kernel 2: attention per (c, b, h). grid = 8192, 128 threads.
// Softmax reductions now parallel (128-thread shfl) instead of t<16 serial.
// ---------------------------------------------------------------------------
__global__ __launch_bounds__(128) void attn_kernel()
{
    int bid = blockIdx.x;
    int h = bid & 7;
    int b = (bid >> 3) & 127;
    int c = bid >> 10;
    int t = threadIdx.x;

    __shared__ float Qs[16 * 64];
    __shared__ float Ks[32 * 68];
    __shared__ float Vs[32 * 64];
    __shared__ float lg[16 * 33];
    __shared__ float rmax[16], rsum[16];

#pragma unroll
    for (int j = 0; j < 2; j++) {
        int i4 = t + 128 * j;
        int nq = i4 >> 4, a4 = i4 & 15;
        *(float4*)&Qs[nq * 64 + a4 * 4] =
            *(const float4*)(g_query + (size_t)((c * NQ_ + nq) * B_ + b) * E_ + h * A_ + a4 * 4);
    }
#pragma unroll
    for (int j = 0; j < 4; j++) {
        int i4 = t + 128 * j;
        int nk = i4 >> 4, a4 = i4 & 15;
        size_t goff = (size_t)((c * NK_ + nk) * B_ + b) * E_ + h * A_ + a4 * 4;
        *(float4*)&Ks[nk * 68 + a4 * 4] = *(const float4*)(g_key + goff);
        *(float4*)&Vs[nk * 64 + a4 * 4] = *(const float4*)(g_value + goff);
    }
    __syncthreads();

    int nk  = t & 31;
    int nq0 = t >> 5;
    {
        float s0 = 0.f, s1 = 0.f, s2 = 0.f, s3 = 0.f;
#pragma unroll
        for (int a4 = 0; a4 < 16; a4++) {
            float4 kv = *(const float4*)&Ks[nk * 68 + a4 * 4];
            float4 q0 = *(const float4*)&Qs[(nq0 + 0)  * 64 + a4 * 4];
            float4 q1 = *(const float4*)&Qs[(nq0 + 4)  * 64 + a4 * 4];
            float4 q2 = *(const float4*)&Qs[(nq0 + 8)  * 64 + a4 * 4];
            float4 q3 = *(const float4*)&Qs[(nq0 + 12) * 64 + a4 * 4];
            s0 += q0.x * kv.x + q0.y * kv.y + q0.z * kv.z + q0.w * kv.w;
            s1 += q1.x * kv.x + q1.y * kv.y + q1.z * kv.z + q1.w * kv.w;
            s2 += q2.x * kv.x + q2.y * kv.y + q2.z * kv.z + q2.w * kv.w;
            s3 += q3.x * kv.x + q3.y * kv.y + q3.z * kv.z + q3.w * kv.w;
        }
        const float inv_temp = 0.125f;
        lg[(nq0 + 0)  * 33 + nk] = s0 * inv_temp;
        lg[(nq0 + 4)  * 33 + nk] = s1 * inv_temp;
        lg[(nq0 + 8)  * 33 + nk] = s2 * inv_temp;
        lg[(nq0 + 12) * 33 + nk] = s3 * inv_temp;
    }
    __syncthreads();

    // Parallel row-max: 8 threads per row (4 elems each), shfl-reduce.
    {
        int r = t >> 3, sub = t & 7;
        const float* row = &lg[r * 33 + sub * 4];
        float m = fmaxf(fmaxf(row[0], row[1]), fmaxf(row[2], row[3]));
        m = fmaxf(m, __shfl_xor_sync(0xffffffffu, m, 1));
        m = fmaxf(m, __shfl_xor_sync(0xffffffffu, m, 2));
        m = fmaxf(m, __shfl_xor_sync(0xffffffffu, m, 4));
        if (sub == 0) rmax[r] = m;
    }
    __syncthreads();

#pragma unroll
    for (int j = 0; j < 4; j++) {
        int nq = nq0 + 4 * j;
        int id = nq * 33 + nk;
        lg[id] = expf(lg[id] - rmax[nq]);
    }
    __syncthreads();

    // Parallel row-sum.
    {
        int r = t >> 3, sub = t & 7;
        const float* row = &lg[r * 33 + sub * 4];
        float s = row[0] + row[1] + row[2] + row[3];
        s += __shfl_xor_sync(0xffffffffu, s, 1);
        s += __shfl_xor_sync(0xffffffffu, s, 2);
        s += __shfl_xor_sync(0xffffffffu, s, 4);
        if (sub == 0) rsum[r] = s;
    }
    __syncthreads();

    int a   = t & 63;
    int nqb = t >> 6;
    float racc[8];
#pragma unroll
    for (int j = 0; j < 8; j++) racc[j] = 0.f;
#pragma unroll
    for (int x = 0; x < 32; x++) {
        float v = Vs[x * 64 + a];
#pragma unroll
        for (int j = 0; j < 8; j++)
            racc[j] += lg[(nqb + 2 * j) * 33 + x] * v;
    }
#pragma unroll
    for (int j = 0; j < 8; j++) {
        int nq = nqb + 2 * j;
        g_attno[(size_t)((c * NQ_ + nq) * B_ + b) * E_ + h * A_ + a] = racc[j] / rsum[nq];
    }
}

// ---------------------------------------------------------------------------
// Kernel 3: split-bf16 HMMA output projection with REGISTER-prefetch
// K-slab pipelining: next slab's raw fp32 A/B loaded by plain LDGs issued
// before the MMA burst (no dependency -> overlapped by scoreboard), split
// into smem only after the burst. Avoids R11's cp.async LSU contention.
// grid = 256: (c, nq, mtile). Block: [64 b x 512 e] @ [512 e x 64 o].
// 256 threads, 8 warps 2(M)x4(N), warp tile 32x16. smem 64 KB -> 2 CTAs/SM.
// ---------------------------------------------------------------------------
#define PJ_AHI   0          // 16 KB  A: [m 64][k 128] bf16
#define PJ_ALO   16384      // 16 KB
#define PJ_BHI   32768      // 16 KB  B: [k 128][n 64] bf16
#define PJ_BLO   49152      // 16 KB
#define PJ_TOTAL 65536

__global__ __launch_bounds__(256, 2) void proj_mma_kernel(
    const float* __restrict__ Wp, float* __restrict__ out)
{
    extern __shared__ char smem[];
    uint32_t sbase = smem_to_u32(smem);
    int t = threadIdx.x, wid = t >> 5, lane = t & 31;

    int bid   = blockIdx.x;
    int mtile = bid & 1;
    int gm    = bid >> 1;
    int nq    = gm & 15;
    int c     = gm >> 4;

    const float* Ap = g_attno + (size_t)((c * NQ_ + nq) * B_ + mtile * 64) * E_;  // ld=512
    const float* Bp = Wp + (size_t)(c * NQ_ + nq) * E_ * OUT_;                    // ld=64
    float*       Op = out + (size_t)((c * NQ_ + nq) * B_ + mtile * 64) * OUT_;    // ld=64

    int m0 = (wid >> 2) * 32;     // 0 or 32
    int n0 = (wid & 3) * 16;      // 0,16,32,48

    int a_row_lo  = lane & 15;
    int a_chsel   = lane >> 4;
    int b_mat     = lane >> 3;
    int b_krow_lo = (b_mat & 1) * 8 + (lane & 7);
    int b_nch     = (n0 >> 3) + (b_mat >> 1);    // 0..7

    float acc[2][2][4];
#pragma unroll
    for (int mt = 0; mt < 2; mt++)
#pragma unroll
        for (int nt = 0; nt < 2; nt++)
#pragma unroll
            for (int r = 0; r < 4; r++) acc[mt][nt][r] = 0.f;

    // Register prefetch buffers: A 8 f4, B 8 f4 (4 items x 2 f4).
    float4 pa[8], pb[8];

    // Prefetch slab 0
#pragma unroll
    for (int j = 0; j < 8; j++) {
        int it = t + 256 * j;                 // row = it>>5 (0..63), kk=(it&31)*4
        pa[j] = *(const float4*)(Ap + (size_t)(it >> 5) * E_ + ((it & 31) * 4));
    }
#pragma unroll
    for (int j = 0; j < 4; j++) {
        int it = t + 256 * j;                 // nch = it&7, krow = it>>3 (0..127)
        const float* src = Bp + (size_t)(it >> 3) * OUT_ + (it & 7) * 8;
        pb[2 * j]     = *(const float4*)(src);
        pb[2 * j + 1] = *(const float4*)(src + 4);
    }

    for (int kslab = 0; kslab < 4; kslab++) {
        if (kslab) __syncthreads();   // MMA on previous tiles done before overwrite

        // ---- Split prefetched regs -> smem tiles ----
#pragma unroll
        for (int j = 0; j < 8; j++) {
            int it  = t + 256 * j;
            int row = it >> 5;
            int kk  = (it & 31) * 4;
            uint32_t h0, l0, h1, l1;
            split2(pa[j].x, pa[j].y, h0, l0);
            split2(pa[j].z, pa[j].w, h1, l1);
            uint32_t off = toff(row, kk);
            *(uint2*)(smem + PJ_AHI + off) = make_uint2(h0, h1);
            *(uint2*)(smem + PJ_ALO + off) = make_uint2(l0, l1);
        }
#pragma unroll
        for (int j = 0; j < 4; j++) {
            int it   = t + 256 * j;
            int nch  = it & 7;
            int krow = it >> 3;
            uint32_t h0, l0, h1, l1, h2, l2, h3, l3;
            split2(pb[2*j].x,   pb[2*j].y,   h0, l0);
            split2(pb[2*j].z,   pb[2*j].w,   h1, l1);
            split2(pb[2*j+1].x, pb[2*j+1].y, h2, l2);
            split2(pb[2*j+1].z, pb[2*j+1].w, h3, l3);
            uint32_t off = ((uint32_t)krow << 7)
                         + ((uint32_t)((nch ^ (krow & 7))) << 4);
            *(uint4*)(smem + PJ_BHI + off) = make_uint4(h0, h1, h2, h3);
            *(uint4*)(smem + PJ_BLO + off) = make_uint4(l0, l1, l2, l3);
        }
        __syncthreads();

        // ---- Prefetch next slab (overlaps the MMA burst below) ----
        if (kslab < 3) {
            const float* An = Ap + (kslab + 1) * 128;
            const float* Bn = Bp + (size_t)(kslab + 1) * 128 * OUT_;
#pragma unroll
            for (int j = 0; j < 8; j++) {
                int it = t + 256 * j;
                pa[j] = *(const float4*)(An + (size_t)(it >> 5) * E_ + ((it & 31) * 4));
            }
#pragma unroll
            for (int j = 0; j < 4; j++) {
                int it = t + 256 * j;
                const float* src = Bn + (size_t)(it >> 3) * OUT_ + (it & 7) * 8;
                pb[2 * j]     = *(const float4*)(src);
                pb[2 * j + 1] = *(const float4*)(src + 4);
            }
        }

        // ---- MMA burst: 8 k-steps x 2x2 tiles x 3 split terms ----
#pragma unroll
        for (int ks = 0; ks < 8; ks++) {
            uint32_t bh[4], bl[4];
            {
                int krow = ks * 16 + b_krow_lo;
                uint32_t off = ((uint32_t)krow << 7)
                             + ((uint32_t)((b_nch ^ (krow & 7))) << 4);
                LDSM_X4_T(bh, sbase + PJ_BHI + off);
                LDSM_X4_T(bl, sbase + PJ_BLO + off);
            }
#pragma unroll
            for (int mt = 0; mt < 2; mt++) {
                int row = m0 + mt * 16 + a_row_lo;
                uint32_t ch = (uint32_t)(ks * 2 + a_chsel);
                uint32_t off = ((uint32_t)row << 8) + (((ch ^ (row & 7))) << 4);
                uint32_t ah[4], al[4];
                LDSM_X4(ah, sbase + PJ_AHI + off);
                LDSM_X4(al, sbase + PJ_ALO + off);
                MMA_BF16(acc[mt][0], ah, bh[0], bh[1]);
                MMA_BF16(acc[mt][0], ah, bl[0], bl[1]);
                MMA_BF16(acc[mt][0], al, bh[0], bh[1]);
                MMA_BF16(acc[mt][1], ah, bh[2], bh[3]);
                MMA_BF16(acc[mt][1], ah, bl[2], bl[3]);
                MMA_BF16(acc[mt][1], al, bh[2], bh[3]);
            }
        }
    }

    // ---- Epilogue ----
#pragma unroll
    for (int mt = 0; mt < 2; mt++) {
        int row = m0 + mt * 16 + (lane >> 2);
#pragma unroll
        for (int nt = 0; nt < 2; nt++) {
            int col = n0 + nt * 8 + (lane & 3) * 2;
            float2 v0 = make_float2(acc[mt][nt][0], acc[mt][nt][1]);
            float2 v1 = make_float2(acc[mt][nt][2], acc[mt][nt][3]);
            *(float2*)(Op + (size_t)row * OUT_ + col) = v0;
            *(float2*)(Op + (size_t)(row + 8) * OUT_ + col) = v1;
        }
    }
}

// ---------------------------------------------------------------------------
extern "C" void kernel_launch(void* const* d_in, const int* in_sizes, int n_in,
                              void* d_out, int out_size)
{
    (void)in_sizes; (void)n_in; (void)out_size;
    const float* q  = (const float*)d_in[0];
    const float* k  = (const float*)d_in[1];
    const float* Wq = (const float*)d_in[2];
    const float* Wk = (const float*)d_in[3];
    const float* Wv = (const float*)d_in[4];
    const float* Wp = (const float*)d_in[5];
    float* out = (float*)d_out;

    cudaFuncSetAttribute(qkv_mma_kernel,
                         cudaFuncAttributeMaxDynamicSharedMemorySize, SM_TOTAL);
    cudaFuncSetAttribute(proj_mma_kernel,
                         cudaFuncAttributeMaxDynamicSharedMemorySize, PJ_TOTAL);

    qkv_mma_kernel<<<640, 512, SM_TOTAL>>>(q, k, Wq, Wk, Wv);
    attn_kernel<<<8192, 128>>>();
    proj_mma_kernel<<<256, 256, PJ_TOTAL>>>(Wp, out);
}

// round 13
// speedup vs baseline: 1.5356x; 1.0250x over previous
#include <cuda_runtime.h>
#include <cuda_bf16.h>
#include <cstdint>
#include <math.h>

// Problem constants
#define C_   8
#define NQ_  16
#define NK_  32
#define B_   128
#define D_   128
#define E_   512
#define H_   8
#define A_   64
#define OUT_ 64

// Scratch (allocation-free rule: device globals)
__device__ float g_query[C_ * NQ_ * B_ * E_];    // 33.5 MB
__device__ float g_key  [C_ * NK_ * B_ * E_];    // 67 MB
__device__ float g_value[C_ * NK_ * B_ * E_];    // 67 MB
__device__ float g_attno[C_ * NQ_ * B_ * E_];    // 33.5 MB

// ===========================================================================
// Helpers
// ===========================================================================
__device__ __forceinline__ uint32_t smem_to_u32(const void* p) {
    uint32_t a;
    asm("{ .reg .u64 t; cvta.to.shared.u64 t, %1; cvt.u32.u64 %0, t; }"
        : "=r"(a) : "l"(p));
    return a;
}

// ldmatrix: 8x8 b16 matrices (baseline PTX, sm_75+)
#define LDSM_X4(r, addr) \
    asm volatile("ldmatrix.sync.aligned.m8n8.x4.shared.b16 {%0,%1,%2,%3}, [%4];" \
        : "=r"((r)[0]), "=r"((r)[1]), "=r"((r)[2]), "=r"((r)[3]) : "r"(addr))
#define LDSM_X4_T(r, addr) \
    asm volatile("ldmatrix.sync.aligned.m8n8.x4.trans.shared.b16 {%0,%1,%2,%3}, [%4];" \
        : "=r"((r)[0]), "=r"((r)[1]), "=r"((r)[2]), "=r"((r)[3]) : "r"(addr))

// mma.sync m16n8k16 bf16 -> f32 (baseline PTX, sm_80+)
#define MMA_BF16(d, a, b0, b1) \
    asm volatile("mma.sync.aligned.m16n8k16.row.col.f32.bf16.bf16.f32 " \
        "{%0,%1,%2,%3}, {%4,%5,%6,%7}, {%8,%9}, {%0,%1,%2,%3};" \
        : "+f"((d)[0]), "+f"((d)[1]), "+f"((d)[2]), "+f"((d)[3]) \
        : "r"((a)[0]), "r"((a)[1]), "r"((a)[2]), "r"((a)[3]), \
          "r"(b0), "r"(b1))

// Tile smem layout: [rows][128 bf16] = 256 B/row, 16B chunks swizzled by
// (chunk ^ (row & 7)) so ldmatrix's 8-row column access is conflict-free.
__device__ __forceinline__ uint32_t toff(int row, int kk) {
    return ((uint32_t)row << 8)
         + ((uint32_t)(((kk >> 3) ^ (row & 7))) << 4)
         + ((uint32_t)(kk & 7) << 1);
}

// Split fp32 pair -> packed bf16x2 hi and lo words
__device__ __forceinline__ void split2(float a, float b, uint32_t& hi, uint32_t& lo) {
    __nv_bfloat16 h0 = __float2bfloat16(a);
    __nv_bfloat16 h1 = __float2bfloat16(b);
    float r0 = a - __bfloat162float(h0);
    float r1 = b - __bfloat162float(h1);
    __nv_bfloat16 l0 = __float2bfloat16(r0);
    __nv_bfloat16 l1 = __float2bfloat16(r1);
    hi = (uint32_t)__bfloat16_as_ushort(h0) | ((uint32_t)__bfloat16_as_ushort(h1) << 16);
    lo = (uint32_t)__bfloat16_as_ushort(l0) | ((uint32_t)__bfloat16_as_ushort(l1) << 16);
}

// ---- qkv dynamic smem layout (bytes) ----
#define SM_PE     0          // 512 B
#define SM_AHI    1024       // 32 KB  A: [m 128][k 128] bf16
#define SM_ALO    33792      // 32 KB
#define SM_BHI    66560      // 2 x 16 KB  B halves: [k 64][n 128] bf16
#define SM_BLO    99328      // 2 x 16 KB
#define SM_TOTAL  132096

// ---------------------------------------------------------------------------
// Kernel 1: split-bf16 HMMA fused QKV projection with positional encoding.
// grid = 640: [0,128) Q, [128,384) K, [384,640) V. 512 threads, 1 CTA/SM.
// NEW (R13): B staged in K-halves (64 rows) with REGISTER prefetch (16 regs)
// + double-buffered smem halves -> the next half's LDGs overlap the current
// half's 4-k-step MMA burst (fix for staging-latency: tensor=38%, issue=17.6%).
// D = Ahi*Bhi + Ahi*Blo + Alo*Bhi, fp32 register accumulate.
// Warp grid 2(M) x 8(N); warp tile 64x16 = 4x2 m16n8 tiles.
// ---------------------------------------------------------------------------
__global__ __launch_bounds__(512, 1) void qkv_mma_kernel(
    const float* __restrict__ q, const float* __restrict__ k,
    const float* __restrict__ Wq, const float* __restrict__ Wk,
    const float* __restrict__ Wv)
{
    extern __shared__ char smem[];
    uint32_t sbase = smem_to_u32(smem);
    int t = threadIdx.x, wid = t >> 5, lane = t & 31;

    int bid = blockIdx.x;
    const float* X; const float* W; float* Out; int n;
    if (bid < 128) {
        int i = bid; int c = i >> 4; n = i & 15;
        X = q  + (size_t)(c * NQ_ + n) * B_ * D_;
        W = Wq + (size_t)(c * NQ_ + n) * D_ * E_;
        Out = g_query + (size_t)(c * NQ_ + n) * B_ * E_;
    } else if (bid < 384) {
        int i = bid - 128; int c = i >> 5; n = i & 31;
        X = k  + (size_t)(c * NK_ + n) * B_ * D_;
        W = Wk + (size_t)(c * NK_ + n) * D_ * E_;
        Out = g_key + (size_t)(c * NK_ + n) * B_ * E_;
    } else {
        int i = bid - 384; int c = i >> 5; n = i & 31;
        X = k  + (size_t)(c * NK_ + n) * B_ * D_;
        W = Wv + (size_t)(c * NK_ + n) * D_ * E_;
        Out = g_value + (size_t)(c * NK_ + n) * B_ * E_;
    }

    // Per-thread staging coordinates for one B K-half (1024 items of 8 floats):
    // item -> (krow 0..63 local, nch 0..15)
    int s_nch  = t & 15;
    int s_kr0  = t >> 4;          // item j adds 32 to krow

    // Register prefetch buffer for one B K-half: 4 float4 = 16 regs.
    float4 pw[4];

    // half-slab index hidx in 0..7: E-slab = hidx>>1, k-base = (hidx&1)*64
#define PREFETCH_W(hidx_) do { \
    const float* _b = W + (size_t)(((hidx_) & 1) * 64) * E_ + ((hidx_) >> 1) * 128; \
    _Pragma("unroll") \
    for (int j = 0; j < 2; j++) { \
        const float* _s = _b + (size_t)(s_kr0 + 32 * j) * E_ + s_nch * 8; \
        pw[2*j]   = *(const float4*)(_s); \
        pw[2*j+1] = *(const float4*)(_s + 4); \
    } \
} while (0)

    // Prefetch slab0/half0 FIRST so its LDGs overlap PE + A staging.
    PREFETCH_W(0);

    float* pe = (float*)(smem + SM_PE);
    if (t < 128) {
        const float kc = -9.210340371976184f / 128.0f;  // -ln(10000)/D
        float w = expf((float)(t & ~1) * kc);
        pe[t] = (t & 1) ? cosf((float)n * w) : sinf((float)n * w);
    }
    __syncthreads();

    // ---- Stage A = X + PE (128 x 128), split hi/lo, [m][k] layout ----
#pragma unroll
    for (int j = 0; j < 8; j++) {
        int it  = t + 512 * j;            // 4096 float4 items
        int row = it >> 5;                // m: 0..127
        int kk  = (it & 31) * 4;          // k: 0..124
        float4 v = *(const float4*)(X + (size_t)row * D_ + kk);
        v.x += pe[kk]; v.y += pe[kk + 1]; v.z += pe[kk + 2]; v.w += pe[kk + 3];
        uint32_t h0, l0, h1, l1;
        split2(v.x, v.y, h0, l0);
        split2(v.z, v.w, h1, l1);
        uint32_t off = toff(row, kk);
        *(uint2*)(smem + SM_AHI + off) = make_uint2(h0, h1);
        *(uint2*)(smem + SM_ALO + off) = make_uint2(l0, l1);
    }

    int m0 = (wid >> 3) * 64;     // warp M origin (0 or 64)
    int n0 = (wid & 7) * 16;      // warp N origin within slab

    int a_row_lo  = lane & 15;
    int a_chsel   = lane >> 4;
    int b_mat     = lane >> 3;
    int b_krow_lo = (b_mat & 1) * 8 + (lane & 7);
    int b_nch     = (n0 >> 3) + (b_mat >> 1);

    for (int slab = 0; slab < 4; slab++) {
        float acc[4][2][4];
#pragma unroll
        for (int mt = 0; mt < 4; mt++)
#pragma unroll
            for (int nt = 0; nt < 2; nt++)
#pragma unroll
                for (int r = 0; r < 4; r++) acc[mt][nt][r] = 0.f;

#pragma unroll
        for (int half = 0; half < 2; half++) {
            int hidx = slab * 2 + half;
            uint32_t bufo = (uint32_t)(hidx & 1) * 16384;

            // ---- Split prefetched regs -> B half buffer ----
#pragma unroll
            for (int j = 0; j < 2; j++) {
                int kr = s_kr0 + 32 * j;      // 0..63
                uint32_t h0, l0, h1, l1, h2, l2, h3, l3;
                split2(pw[2*j].x,   pw[2*j].y,   h0, l0);
                split2(pw[2*j].z,   pw[2*j].w,   h1, l1);
                split2(pw[2*j+1].x, pw[2*j+1].y, h2, l2);
                split2(pw[2*j+1].z, pw[2*j+1].w, h3, l3);
                uint32_t off = ((uint32_t)kr << 8)
                             + ((uint32_t)((s_nch ^ (kr & 7))) << 4);
                *(uint4*)(smem + SM_BHI + bufo + off) = make_uint4(h0, h1, h2, h3);
                *(uint4*)(smem + SM_BLO + bufo + off) = make_uint4(l0, l1, l2, l3);
            }
            __syncthreads();

            // ---- Prefetch next K-half (overlaps the burst below) ----
            if (hidx < 7) PREFETCH_W(hidx + 1);

            // ---- MMA burst: 4 k-steps x 4x2 tiles x 3 split terms ----
#pragma unroll
            for (int ks = 0; ks < 4; ks++) {
                uint32_t bh[4], bl[4];
                {
                    int krow = ks * 16 + b_krow_lo;   // local to half buffer
                    uint32_t off = ((uint32_t)krow << 8)
                                 + ((uint32_t)((b_nch ^ (krow & 7))) << 4);
                    LDSM_X4_T(bh, sbase + SM_BHI + bufo + off);
                    LDSM_X4_T(bl, sbase + SM_BLO + bufo + off);
                }
#pragma unroll
                for (int mt = 0; mt < 4; mt++) {
                    int row = m0 + mt * 16 + a_row_lo;
                    uint32_t ch = (uint32_t)((half * 4 + ks) * 2 + a_chsel);
                    uint32_t off = ((uint32_t)row << 8) + (((ch ^ (row & 7))) << 4);
                    uint32_t ah[4], al[4];
                    LDSM_X4(ah, sbase + SM_AHI + off);
                    LDSM_X4(al, sbase + SM_ALO + off);
                    MMA_BF16(acc[mt][0], ah, bh[0], bh[1]);
                    MMA_BF16(acc[mt][0], ah, bl[0], bl[1]);
                    MMA_BF16(acc[mt][0], al, bh[0], bh[1]);
                    MMA_BF16(acc[mt][1], ah, bh[2], bh[3]);
                    MMA_BF16(acc[mt][1], ah, bl[2], bl[3]);
                    MMA_BF16(acc[mt][1], al, bh[2], bh[3]);
                }
            }
        }

        // ---- Epilogue: direct fp32 stores for this slab ----
#pragma unroll
        for (int mt = 0; mt < 4; mt++) {
            int row = m0 + mt * 16 + (lane >> 2);
#pragma unroll
            for (int nt = 0; nt < 2; nt++) {
                int col = slab * 128 + n0 + nt * 8 + (lane & 3) * 2;
                float2 v0 = make_float2(acc[mt][nt][0], acc[mt][nt][1]);
                float2 v1 = make_float2(acc[mt][nt][2], acc[mt][nt][3]);
                *(float2*)(Out + (size_t)row * E_ + col) = v0;
                *(float2*)(Out + (size_t)(row + 8) * E_ + col) = v1;
            }
        }
    }
#undef PREFETCH_W
}

// ---------------------------------------------------------------------------
// Kernel 2: attention per (c, b, h). grid = 8192, 128 threads. (R12 version)
// ---------------------------------------------------------------------------
__global__ __launch_bounds__(128) void attn_kernel()
{
    int bid = blockIdx.x;
    int h = bid & 7;
    int b = (bid >> 3) & 127;
    int c = bid >> 10;
    int t = threadIdx.x;

    __shared__ float Qs[16 * 64];
    __shared__ float Ks[32 * 68];
    __shared__ float Vs[32 * 64];
    __shared__ float lg[16 * 33];
    __shared__ float rmax[16], rsum[16];

#pragma unroll
    for (int j = 0; j < 2; j++) {
        int i4 = t + 128 * j;
        int nq = i4 >> 4, a4 = i4 & 15;
        *(float4*)&Qs[nq * 64 + a4 * 4] =
            *(const float4*)(g_query + (size_t)((c * NQ_ + nq) * B_ + b) * E_ + h * A_ + a4 * 4);
    }
#pragma unroll
    for (int j = 0; j < 4; j++) {
        int i4 = t + 128 * j;
        int nk = i4 >> 4, a4 = i4 & 15;
        size_t goff = (size_t)((c * NK_ + nk) * B_ + b) * E_ + h * A_ + a4 * 4;
        *(float4*)&Ks[nk * 68 + a4 * 4] = *(const float4*)(g_key + goff);
        *(float4*)&Vs[nk * 64 + a4 * 4] = *(const float4*)(g_value + goff);
    }
    __syncthreads();

    int nk  = t & 31;
    int nq0 = t >> 5;
    {
        float s0 = 0.f, s1 = 0.f, s2 = 0.f, s3 = 0.f;
#pragma unroll
        for (int a4 = 0; a4 < 16; a4++) {
            float4 kv = *(const float4*)&Ks[nk * 68 + a4 * 4];
            float4 q0 = *(const float4*)&Qs[(nq0 + 0)  * 64 + a4 * 4];
            float4 q1 = *(const float4*)&Qs[(nq0 + 4)  * 64 + a4 * 4];
            float4 q2 = *(const float4*)&Qs[(nq0 + 8)  * 64 + a4 * 4];
            float4 q3 = *(const float4*)&Qs[(nq0 + 12) * 64 + a4 * 4];
            s0 += q0.x * kv.x + q0.y * kv.y + q0.z * kv.z + q0.w * kv.w;
            s1 += q1.x * kv.x + q1.y * kv.y + q1.z * kv.z + q1.w * kv.w;
            s2 += q2.x * kv.x + q2.y * kv.y + q2.z * kv.z + q2.w * kv.w;
            s3 += q3.x * kv.x + q3.y * kv.y + q3.z * kv.z + q3.w * kv.w;
        }
        const float inv_temp = 0.125f;
        lg[(nq0 + 0)  * 33 + nk] = s0 * inv_temp;
        lg[(nq0 + 4)  * 33 + nk] = s1 * inv_temp;
        lg[(nq0 + 8)  * 33 + nk] = s2 * inv_temp;
        lg[(nq0 + 12) * 33 + nk] = s3 * inv_temp;
    }
    __syncthreads();

    {
        int r = t >> 3, sub = t & 7;
        const float* row = &lg[r * 33 + sub * 4];
        float m = fmaxf(fmaxf(row[0], row[1]), fmaxf(row[2], row[3]));
        m = fmaxf(m, __shfl_xor_sync(0xffffffffu, m, 1));
        m = fmaxf(m, __shfl_xor_sync(0xffffffffu, m, 2));
        m = fmaxf(m, __shfl_xor_sync(0xffffffffu, m, 4));
        if (sub == 0) rmax[r] = m;
    }
    __syncthreads();

#pragma unroll
    for (int j = 0; j < 4; j++) {
        int nq = nq0 + 4 * j;
        int id = nq * 33 + nk;
        lg[id] = expf(lg[id] - rmax[nq]);
    }
    __syncthreads();

    {
        int r = t >> 3, sub = t & 7;
        const float* row = &lg[r * 33 + sub * 4];
        float s = row[0] + row[1] + row[2] + row[3];
        s += __shfl_xor_sync(0xffffffffu, s, 1);
        s += __shfl_xor_sync(0xffffffffu, s, 2);
        s += __shfl_xor_sync(0xffffffffu, s, 4);
        if (sub == 0) rsum[r] = s;
    }
    __syncthreads();

    int a   = t & 63;
    int nqb = t >> 6;
    float racc[8];
#pragma unroll
    for (int j = 0; j < 8; j++) racc[j] = 0.f;
#pragma unroll
    for (int x = 0; x < 32; x++) {
        float v = Vs[x * 64 + a];
#pragma unroll
        for (int j = 0; j < 8; j++)
            racc[j] += lg[(nqb + 2 * j) * 33 + x] * v;
    }
#pragma unroll
    for (int j = 0; j < 8; j++) {
        int nq = nqb + 2 * j;
        g_attno[(size_t)((c * NQ_ + nq) * B_ + b) * E_ + h * A_ + a] = racc[j] / rsum[nq];
    }
}

// ---------------------------------------------------------------------------
// Kernel 3: split-bf16 HMMA output projection with register-prefetch
// K-slab pipelining. (R12 version, unchanged — validated win.)
// ---------------------------------------------------------------------------
#define PJ_AHI   0          // 16 KB  A: [m 64][k 128] bf16
#define PJ_ALO   16384      // 16 KB
#define PJ_BHI   32768      // 16 KB  B: [k 128][n 64] bf16
#define PJ_BLO   49152      // 16 KB
#define PJ_TOTAL 65536

__global__ __launch_bounds__(256, 2) void proj_mma_kernel(
    const float* __restrict__ Wp, float* __restrict__ out)
{
    extern __shared__ char smem[];
    uint32_t sbase = smem_to_u32(smem);
    int t = threadIdx.x, wid = t >> 5, lane = t & 31;

    int bid   = blockIdx.x;
    int mtile = bid & 1;
    int gm    = bid >> 1;
    int nq    = gm & 15;
    int c     = gm >> 4;

    const float* Ap = g_attno + (size_t)((c * NQ_ + nq) * B_ + mtile * 64) * E_;
    const float* Bp = Wp + (size_t)(c * NQ_ + nq) * E_ * OUT_;
    float*       Op = out + (size_t)((c * NQ_ + nq) * B_ + mtile * 64) * OUT_;

    int m0 = (wid >> 2) * 32;
    int n0 = (wid & 3) * 16;

    int a_row_lo  = lane & 15;
    int a_chsel   = lane >> 4;
    int b_mat     = lane >> 3;
    int b_krow_lo = (b_mat & 1) * 8 + (lane & 7);
    int b_nch     = (n0 >> 3) + (b_mat >> 1);

    float acc[2][2][4];
#pragma unroll
    for (int mt = 0; mt < 2; mt++)
#pragma unroll
        for (int nt = 0; nt < 2; nt++)
#pragma unroll
            for (int r = 0; r < 4; r++) acc[mt][nt][r] = 0.f;

    float4 pa[8], pb[8];

#pragma unroll
    for (int j = 0; j < 8; j++) {
        int it = t + 256 * j;
        pa[j] = *(const float4*)(Ap + (size_t)(it >> 5) * E_ + ((it & 31) * 4));
    }
#pragma unroll
    for (int j = 0; j < 4; j++) {
        int it = t + 256 * j;
        const float* src = Bp + (size_t)(it >> 3) * OUT_ + (it & 7) * 8;
        pb[2 * j]     = *(const float4*)(src);
        pb[2 * j + 1] = *(const float4*)(src + 4);
    }

    for (int kslab = 0; kslab < 4; kslab++) {
        if (kslab) __syncthreads();

#pragma unroll
        for (int j = 0; j < 8; j++) {
            int it  = t + 256 * j;
            int row = it >> 5;
            int kk  = (it & 31) * 4;
            uint32_t h0, l0, h1, l1;
            split2(pa[j].x, pa[j].y, h0, l0);
            split2(pa[j].z, pa[j].w, h1, l1);
            uint32_t off = toff(row, kk);
            *(uint2*)(smem + PJ_AHI + off) = make_uint2(h0, h1);
            *(uint2*)(smem + PJ_ALO + off) = make_uint2(l0, l1);
        }
#pragma unroll
        for (int j = 0; j < 4; j++) {
            int it   = t + 256 * j;
            int nch  = it & 7;
            int krow = it >> 3;
            uint32_t h0, l0, h1, l1, h2, l2, h3, l3;
            split2(pb[2*j].x,   pb[2*j].y,   h0, l0);
            split2(pb[2*j].z,   pb[2*j].w,   h1, l1);
            split2(pb[2*j+1].x, pb[2*j+1].y, h2, l2);
            split2(pb[2*j+1].z, pb[2*j+1].w, h3, l3);
            uint32_t off = ((uint32_t)krow << 7)
                         + ((uint32_t)((nch ^ (krow & 7))) << 4);
            *(uint4*)(smem + PJ_BHI + off) = make_uint4(h0, h1, h2, h3);
            *(uint4*)(smem + PJ_BLO + off) = make_uint4(l0, l1, l2, l3);
        }
        __syncthreads();

        if (kslab < 3) {
            const float* An = Ap + (kslab + 1) * 128;
            const float* Bn = Bp + (size_t)(kslab + 1) * 128 * OUT_;
#pragma unroll
            for (int j = 0; j < 8; j++) {
                int it = t + 256 * j;
                pa[j] = *(const float4*)(An + (size_t)(it >> 5) * E_ + ((it & 31) * 4));
            }
#pragma unroll
            for (int j = 0; j < 4; j++) {
                int it = t + 256 * j;
                const float* src = Bn + (size_t)(it >> 3) * OUT_ + (it & 7) * 8;
                pb[2 * j]     = *(const float4*)(src);
                pb[2 * j + 1] = *(const float4*)(src + 4);
            }
        }

#pragma unroll
        for (int ks = 0; ks < 8; ks++) {
            uint32_t bh[4], bl[4];
            {
                int krow = ks * 16 + b_krow_lo;
                uint32_t off = ((uint32_t)krow << 7)
                             + ((uint32_t)((b_nch ^ (krow & 7))) << 4);
                LDSM_X4_T(bh, sbase + PJ_BHI + off);
                LDSM_X4_T(bl, sbase + PJ_BLO + off);
            }
#pragma unroll
            for (int mt = 0; mt < 2; mt++) {
                int row = m0 + mt * 16 + a_row_lo;
                uint32_t ch = (uint32_t)(ks * 2 + a_chsel);
                uint32_t off = ((uint32_t)row << 8) + (((ch ^ (row & 7))) << 4);
                uint32_t ah[4], al[4];
                LDSM_X4(ah, sbase + PJ_AHI + off);
                LDSM_X4(al, sbase + PJ_ALO + off);
                MMA_BF16(acc[mt][0], ah, bh[0], bh[1]);
                MMA_BF16(acc[mt][0], ah, bl[0], bl[1]);
                MMA_BF16(acc[mt][0], al, bh[0], bh[1]);
                MMA_BF16(acc[mt][1], ah, bh[2], bh[3]);
                MMA_BF16(acc[mt][1], ah, bl[2], bl[3]);
                MMA_BF16(acc[mt][1], al, bh[2], bh[3]);
            }
        }
    }

#pragma unroll
    for (int mt = 0; mt < 2; mt++) {
        int row = m0 + mt * 16 + (lane >> 2);
#pragma unroll
        for (int nt = 0; nt < 2; nt++) {
            int col = n0 + nt * 8 + (lane & 3) * 2;
            float2 v0 = make_float2(acc[mt][nt][0], acc[mt][nt][1]);
            float2 v1 = make_float2(acc[mt][nt][2], acc[mt][nt][3]);
            *(float2*)(Op + (size_t)row * OUT_ + col) = v0;
            *(float2*)(Op + (size_t)(row + 8) * OUT_ + col) = v1;
        }
    }
}

// ---------------------------------------------------------------------------
extern "C" void kernel_launch(void* const* d_in, const int* in_sizes, int n_in,
                              void* d_out, int out_size)
{
    (void)in_sizes; (void)n_in; (void)out_size;
    const float* q  = (const float*)d_in[0];
    const float* k  = (const float*)d_in[1];
    const float* Wq = (const float*)d_in[2];
    const float* Wk = (const float*)d_in[3];
    const float* Wv = (const float*)d_in[4];
    const float* Wp = (const float*)d_in[5];
    float* out = (float*)d_out;

    cudaFuncSetAttribute(qkv_mma_kernel,
                         cudaFuncAttributeMaxDynamicSharedMemorySize, SM_TOTAL);
    cudaFuncSetAttribute(proj_mma_kernel,
                         cudaFuncAttributeMaxDynamicSharedMemorySize, PJ_TOTAL);

    qkv_mma_kernel<<<640, 512, SM_TOTAL>>>(q, k, Wq, Wk, Wv);
    attn_kernel<<<8192, 128>>>();
    proj_mma_kernel<<<256, 256, PJ_TOTAL>>>(Wp, out);
}